// round 3
// baseline (speedup 1.0000x reference)
#include <cuda_runtime.h>
#include <math.h>

#define NN 100000
#define EE 1600000
#define RR 8
#define GG 128
#define HH 64
#define CC 512   // RR*HH

// ---------------- scratch (device globals; no runtime allocation) ----------------
__device__ float g_xw[(size_t)RR * NN * HH];   // [r][n][h], h contiguous (204.8 MB)
__device__ float g_WT[GG * CC];                // transposed weights [K][r*64+o]
__device__ float g_sq[RR * NN];                // xw . q  per (r,n)
__device__ float g_sk[RR * NN];                // xw . k  per (r,n)
__device__ float g_alpha[EE];
__device__ int   g_rs[EE];                     // r*N + src
__device__ int   g_rd[EE];                     // r*N + dst
__device__ int   g_dstl[EE];                   // dst
__device__ float g_m[NN];
__device__ float g_denom[NN];
__device__ float g_agg[NN * HH];
__device__ float g_x1[NN * HH];
__device__ float g_bnsum[HH];
__device__ float g_bnsqs[HH];
__device__ float g_bnscale[HH];
__device__ float g_bnshift[HH];

// ---------------- kernels ----------------

// edge_index / edge_type are int32 (JAX x64 disabled downgrades int64->int32).
__global__ void k_decode(const int* __restrict__ ei,
                         const int* __restrict__ et) {
    int e = blockIdx.x * blockDim.x + threadIdx.x;
    if (e >= EE) return;
    int s = ei[e];
    int d = ei[EE + e];
    int r = et[e];
    // branch-free clamp: wrong dtype degrades to wrong values, not a trap
    s = min(max(s, 0), NN - 1);
    d = min(max(d, 0), NN - 1);
    r = min(max(r, 0), RR - 1);
    g_rs[e]   = r * NN + s;
    g_rd[e]   = r * NN + d;
    g_dstl[e] = d;
}

__global__ void k_init() {
    int i = blockIdx.x * blockDim.x + threadIdx.x;   // NN*16 threads
    if (i < NN * (HH / 4)) ((float4*)g_agg)[i] = make_float4(0.f, 0.f, 0.f, 0.f);
    if (i < NN) { g_m[i] = -INFINITY; g_denom[i] = 0.f; }
    if (i < HH) { g_bnsum[i] = 0.f; g_bnsqs[i] = 0.f; }
}

// W [R,K,H] -> WT [K, r*64+o]
__global__ void k_wt(const float* __restrict__ W, int K) {
    int idx = blockIdx.x * blockDim.x + threadIdx.x;
    if (idx >= K * CC) return;
    int i = idx / CC, c = idx % CC;
    int r = c >> 6, o = c & 63;
    g_WT[idx] = W[((size_t)r * K + i) * HH + o];
}

// C[n, r*64+o] = sum_k A[n,k] * WT[k, r*64+o], written to g_xw[(r*N+n)*64+o]
// block: 128 rows x 64 cols (one relation), 256 threads, 8x4 per-thread tile.
__global__ void k_gemm(const float* __restrict__ Aparam, int M, int K, int useX1) {
    const float* __restrict__ A = useX1 ? g_x1 : Aparam;
    __shared__ float As[16][128];
    __shared__ float Bs[16][64 + 4];
    int r = blockIdx.x;                  // relation = column block
    int rowBase = blockIdx.y * 128;
    int tid = threadIdx.x;
    int ty = tid >> 4, tx = tid & 15;
    float acc[8][4] = {};
    for (int kt = 0; kt < K; kt += 16) {
        // load A tile (128x16), 2 passes of 64 rows, float4 per thread
        #pragma unroll
        for (int p = 0; p < 2; p++) {
            int rI = (tid >> 2) + p * 64;
            int kv = (tid & 3) * 4;
            int grow = rowBase + rI;
            float4 v = make_float4(0.f, 0.f, 0.f, 0.f);
            if (grow < M) v = *(const float4*)(A + (size_t)grow * K + kt + kv);
            As[kv + 0][rI] = v.x; As[kv + 1][rI] = v.y;
            As[kv + 2][rI] = v.z; As[kv + 3][rI] = v.w;
        }
        // load B tile (16x64)
        {
            int kk = tid >> 4;
            int cv = (tid & 15) * 4;
            float4 v = *(const float4*)(g_WT + (size_t)(kt + kk) * CC + r * 64 + cv);
            Bs[kk][cv + 0] = v.x; Bs[kk][cv + 1] = v.y;
            Bs[kk][cv + 2] = v.z; Bs[kk][cv + 3] = v.w;
        }
        __syncthreads();
        #pragma unroll
        for (int k = 0; k < 16; k++) {
            float a[8], b[4];
            #pragma unroll
            for (int i = 0; i < 8; i++) a[i] = As[k][ty * 8 + i];
            #pragma unroll
            for (int j = 0; j < 4; j++) b[j] = Bs[k][tx * 4 + j];
            #pragma unroll
            for (int i = 0; i < 8; i++)
                #pragma unroll
                for (int j = 0; j < 4; j++) acc[i][j] += a[i] * b[j];
        }
        __syncthreads();
    }
    #pragma unroll
    for (int i = 0; i < 8; i++) {
        int row = rowBase + ty * 8 + i;
        if (row < M) {
            float4 v = make_float4(acc[i][0], acc[i][1], acc[i][2], acc[i][3]);
            *(float4*)(g_xw + ((size_t)r * NN + row) * 64 + tx * 4) = v;
        }
    }
}

// s_q[rn] = xw[rn,:].q ; s_k[rn] = xw[rn,:].k  — one warp per (r,n)
__global__ void k_scores(const float* __restrict__ q, const float* __restrict__ k) {
    int warp = (blockIdx.x * blockDim.x + threadIdx.x) >> 5;
    int lane = threadIdx.x & 31;
    if (warp >= RR * NN) return;
    float2 v  = ((const float2*)(g_xw + (size_t)warp * 64))[lane];
    float2 qv = ((const float2*)q)[lane];
    float2 kv = ((const float2*)k)[lane];
    float dq = v.x * qv.x + v.y * qv.y;
    float dk = v.x * kv.x + v.y * kv.y;
    #pragma unroll
    for (int off = 16; off; off >>= 1) {
        dq += __shfl_down_sync(0xffffffffu, dq, off);
        dk += __shfl_down_sync(0xffffffffu, dk, off);
    }
    if (lane == 0) { g_sq[warp] = dq; g_sk[warp] = dk; }
}

__global__ void k_passA() {
    int e = blockIdx.x * blockDim.x + threadIdx.x;
    if (e >= EE) return;
    float a = g_sq[g_rd[e]] + g_sk[g_rs[e]];
    a = a > 0.f ? a : 0.2f * a;           // leaky_relu slope 0.2
    g_alpha[e] = a;
    float* addr = &g_m[g_dstl[e]];
    if (a >= 0.f) atomicMax((int*)addr, __float_as_int(a));
    else          atomicMin((unsigned int*)addr, __float_as_uint(a));
}

// 16 lanes per edge: w = exp(alpha - m[dst]); agg[dst] += w * xw[r,src,:]
__global__ void k_passB() {
    int t = blockIdx.x * blockDim.x + threadIdx.x;
    int e = t >> 4;
    int l = t & 15;
    if (e >= EE) return;
    int d = g_dstl[e];
    float w = expf(g_alpha[e] - g_m[d]);
    if (l == 0) atomicAdd(&g_denom[d], w);
    float4 v = *(const float4*)(g_xw + (size_t)g_rs[e] * 64 + l * 4);
    float* dst = g_agg + (size_t)d * 64 + l * 4;
    atomicAdd(dst + 0, v.x * w);
    atomicAdd(dst + 1, v.y * w);
    atomicAdd(dst + 2, v.z * w);
    atomicAdd(dst + 3, v.w * w);
}

__global__ void k_finish1(const float* __restrict__ b) {
    int t = blockIdx.x * blockDim.x + threadIdx.x;
    if (t >= NN * 16) return;
    int n = t >> 4, h4 = t & 15;
    float4 v = ((float4*)g_agg)[t];
    float inv = 1.f / (g_denom[n] + 1e-16f);
    float4 bb = ((const float4*)b)[h4];
    v.x = fmaxf(v.x * inv + bb.x, 0.f);
    v.y = fmaxf(v.y * inv + bb.y, 0.f);
    v.z = fmaxf(v.z * inv + bb.z, 0.f);
    v.w = fmaxf(v.w * inv + bb.w, 0.f);
    ((float4*)g_x1)[t] = v;
}

__global__ void k_finish2(const float* __restrict__ b, float* __restrict__ out) {
    __shared__ float ssum[HH], ssq[HH];
    int tid = threadIdx.x;
    if (tid < HH) { ssum[tid] = 0.f; ssq[tid] = 0.f; }
    __syncthreads();
    int t = blockIdx.x * blockDim.x + tid;
    if (t < NN * 16) {
        int n = t >> 4, h4 = t & 15;
        float4 v = ((float4*)g_agg)[t];
        float inv = 1.f / (g_denom[n] + 1e-16f);
        float4 bb = ((const float4*)b)[h4];
        v.x = v.x * inv + bb.x;
        v.y = v.y * inv + bb.y;
        v.z = v.z * inv + bb.z;
        v.w = v.w * inv + bb.w;
        ((float4*)out)[t] = v;
        int h = h4 * 4;
        atomicAdd(&ssum[h + 0], v.x); atomicAdd(&ssq[h + 0], v.x * v.x);
        atomicAdd(&ssum[h + 1], v.y); atomicAdd(&ssq[h + 1], v.y * v.y);
        atomicAdd(&ssum[h + 2], v.z); atomicAdd(&ssq[h + 2], v.z * v.z);
        atomicAdd(&ssum[h + 3], v.w); atomicAdd(&ssq[h + 3], v.w * v.w);
    }
    __syncthreads();
    if (tid < HH) {
        atomicAdd(&g_bnsum[tid], ssum[tid]);
        atomicAdd(&g_bnsqs[tid], ssq[tid]);
    }
}

__global__ void k_bnfinal(const float* __restrict__ gamma, const float* __restrict__ beta) {
    int h = threadIdx.x;
    if (h < HH) {
        float mean = g_bnsum[h] * (1.f / NN);
        float var  = g_bnsqs[h] * (1.f / NN) - mean * mean;
        float sc = gamma[h] * rsqrtf(var + 1e-5f);
        g_bnscale[h] = sc;
        g_bnshift[h] = beta[h] - mean * sc;
    }
}

__global__ void k_bnapply(float* __restrict__ out) {
    int t = blockIdx.x * blockDim.x + threadIdx.x;
    if (t >= NN * 16) return;
    int h4 = t & 15;
    float4 v  = ((float4*)out)[t];
    float4 sc = ((const float4*)g_bnscale)[h4];
    float4 sh = ((const float4*)g_bnshift)[h4];
    v.x = v.x * sc.x + sh.x; v.x = v.x > 0.f ? v.x : 0.01f * v.x;
    v.y = v.y * sc.y + sh.y; v.y = v.y > 0.f ? v.y : 0.01f * v.y;
    v.z = v.z * sc.z + sh.z; v.z = v.z > 0.f ? v.z : 0.01f * v.z;
    v.w = v.w * sc.w + sh.w; v.w = v.w > 0.f ? v.w : 0.01f * v.w;
    ((float4*)out)[t] = v;
}

// ---------------- launch ----------------
extern "C" void kernel_launch(void* const* d_in, const int* in_sizes, int n_in,
                              void* d_out, int out_size) {
    const float* x     = (const float*)d_in[0];
    const int*   ei    = (const int*)d_in[1];   // int32 (JAX x64 disabled)
    const int*   et    = (const int*)d_in[2];   // int32
    const float* W1    = (const float*)d_in[3];
    const float* q1    = (const float*)d_in[4];
    const float* k1    = (const float*)d_in[5];
    const float* b1    = (const float*)d_in[6];
    const float* W2    = (const float*)d_in[7];
    const float* q2    = (const float*)d_in[8];
    const float* k2    = (const float*)d_in[9];
    const float* b2    = (const float*)d_in[10];
    const float* gamma = (const float*)d_in[11];
    const float* beta  = (const float*)d_in[12];
    float* out = (float*)d_out;

    const int TPB = 256;
    dim3 gemmGrid(RR, (NN + 127) / 128);

    k_decode<<<(EE + TPB - 1) / TPB, TPB>>>(ei, et);

    // ---- layer 1 ----
    k_init<<<(NN * 16 + TPB - 1) / TPB, TPB>>>();
    k_wt<<<(GG * CC + TPB - 1) / TPB, TPB>>>(W1, GG);
    k_gemm<<<gemmGrid, TPB>>>(x, NN, GG, 0);
    k_scores<<<(RR * NN * 32) / TPB, TPB>>>(q1, k1);
    k_passA<<<(EE + TPB - 1) / TPB, TPB>>>();
    k_passB<<<(EE * 16 + TPB - 1) / TPB, TPB>>>();
    k_finish1<<<(NN * 16 + TPB - 1) / TPB, TPB>>>(b1);

    // ---- layer 2 ----
    k_init<<<(NN * 16 + TPB - 1) / TPB, TPB>>>();
    k_wt<<<(HH * CC + TPB - 1) / TPB, TPB>>>(W2, HH);
    k_gemm<<<gemmGrid, TPB>>>(nullptr, NN, HH, 1);
    k_scores<<<(RR * NN * 32) / TPB, TPB>>>(q2, k2);
    k_passA<<<(EE + TPB - 1) / TPB, TPB>>>();
    k_passB<<<(EE * 16 + TPB - 1) / TPB, TPB>>>();
    k_finish2<<<(NN * 16 + TPB - 1) / TPB, TPB>>>(b2, out);

    // ---- batchnorm + leaky ----
    k_bnfinal<<<1, HH>>>(gamma, beta);
    k_bnapply<<<(NN * 16 + TPB - 1) / TPB, TPB>>>(out);
}

// round 5
// speedup vs baseline: 1.4420x; 1.4420x over previous
#include <cuda_runtime.h>
#include <math.h>

#define NN 100000
#define EE 1600000
#define RR 8
#define GG 128
#define HH 64
#define CC 512   // RR*HH
#define SCAN_B 512
#define NBLK ((NN + SCAN_B - 1) / SCAN_B)   // 196

// ---------------- scratch ----------------
__device__ float g_xw[(size_t)RR * NN * HH];   // [r][n][h]
__device__ float g_WT[GG * CC];
__device__ float g_sq[RR * NN];
__device__ float g_sk[RR * NN];
__device__ int   g_rs[EE];                     // r*N + src
__device__ int   g_dstl[EE];
__device__ int   g_sorted[EE];                 // rs sorted by dst
__device__ int   g_cnt[NN];
__device__ int   g_wpos[NN];
__device__ int   g_off[NN];
__device__ int   g_scan[NN];
__device__ int   g_bsum[256];
__device__ int   g_bpre[256];
__device__ float g_x1[NN * HH];
__device__ float g_bnsum[HH];
__device__ float g_bnsqs[HH];
__device__ float g_bnscale[HH];
__device__ float g_bnshift[HH];

// ---------------- sort-by-dst pipeline ----------------
__global__ void k_zero() {
    int i = blockIdx.x * blockDim.x + threadIdx.x;
    if (i < NN) { g_cnt[i] = 0; g_wpos[i] = 0; }
    if (i < HH) { g_bnsum[i] = 0.f; g_bnsqs[i] = 0.f; }
}

__global__ void k_decode(const int* __restrict__ ei, const int* __restrict__ et) {
    int e = blockIdx.x * blockDim.x + threadIdx.x;
    if (e >= EE) return;
    int s = min(max(ei[e], 0), NN - 1);
    int d = min(max(ei[EE + e], 0), NN - 1);
    int r = min(max(et[e], 0), RR - 1);
    g_rs[e]   = r * NN + s;
    g_dstl[e] = d;
    atomicAdd(&g_cnt[d], 1);
}

__global__ void k_scan1() {
    __shared__ int s[SCAN_B];
    int tid = threadIdx.x;
    int i = blockIdx.x * SCAN_B + tid;
    int v = (i < NN) ? g_cnt[i] : 0;
    s[tid] = v;
    __syncthreads();
    for (int d = 1; d < SCAN_B; d <<= 1) {
        int t = (tid >= d) ? s[tid - d] : 0;
        __syncthreads();
        s[tid] += t;
        __syncthreads();
    }
    if (i < NN) g_scan[i] = s[tid];
    if (tid == SCAN_B - 1) g_bsum[blockIdx.x] = s[tid];
}

__global__ void k_scan2() {
    __shared__ int s[256];
    int tid = threadIdx.x;
    int v = (tid < NBLK) ? g_bsum[tid] : 0;
    s[tid] = v;
    __syncthreads();
    for (int d = 1; d < 256; d <<= 1) {
        int t = (tid >= d) ? s[tid - d] : 0;
        __syncthreads();
        s[tid] += t;
        __syncthreads();
    }
    if (tid < NBLK) g_bpre[tid] = s[tid] - v;   // exclusive
}

__global__ void k_scan3() {
    int i = blockIdx.x * blockDim.x + threadIdx.x;
    if (i >= NN) return;
    g_off[i] = g_scan[i] - g_cnt[i] + g_bpre[i >> 9];   // exclusive offsets
}

__global__ void k_scatter() {
    int e = blockIdx.x * blockDim.x + threadIdx.x;
    if (e >= EE) return;
    int d = g_dstl[e];
    int pos = g_off[d] + atomicAdd(&g_wpos[d], 1);
    g_sorted[pos] = g_rs[e];
}

// ---------------- GEMM: 128 rows x 128 cols (2 relations), 8x8/thread ----------------
// W [R,K,H] -> WT [K, r*64+o]
__global__ void k_wt(const float* __restrict__ W, int K) {
    int idx = blockIdx.x * blockDim.x + threadIdx.x;
    if (idx >= K * CC) return;
    int i = idx / CC, c = idx % CC;
    int r = c >> 6, o = c & 63;
    g_WT[idx] = W[((size_t)r * K + i) * HH + o];
}

__global__ void k_gemm(const float* __restrict__ Aparam, int M, int K, int useX1) {
    const float* __restrict__ A = useX1 ? g_x1 : Aparam;
    __shared__ float As[16][132];
    __shared__ float Bs[16][132];
    int rp = blockIdx.x;                 // relation pair: relations 2rp, 2rp+1
    int rowBase = blockIdx.y * 128;
    int tid = threadIdx.x;
    int ty = tid >> 4, tx = tid & 15;
    float acc[8][8] = {};
    for (int kt = 0; kt < K; kt += 16) {
        #pragma unroll
        for (int p = 0; p < 2; p++) {
            int idx = tid + p * 256;
            int row = idx >> 2;
            int kq = (idx & 3) * 4;
            int grow = rowBase + row;
            float4 v = make_float4(0.f, 0.f, 0.f, 0.f);
            if (grow < M) v = *(const float4*)(A + (size_t)grow * K + kt + kq);
            As[kq + 0][row] = v.x; As[kq + 1][row] = v.y;
            As[kq + 2][row] = v.z; As[kq + 3][row] = v.w;
        }
        #pragma unroll
        for (int p = 0; p < 2; p++) {
            int idx = tid + p * 256;
            int kk = idx >> 5;
            int c4 = (idx & 31) * 4;
            float4 v = *(const float4*)(g_WT + (size_t)(kt + kk) * CC + rp * 128 + c4);
            *(float4*)&Bs[kk][c4] = v;
        }
        __syncthreads();
        #pragma unroll
        for (int k = 0; k < 16; k++) {
            float4 a0 = *(float4*)&As[k][ty * 8];
            float4 a1 = *(float4*)&As[k][ty * 8 + 4];
            float4 b0 = *(float4*)&Bs[k][tx * 4];
            float4 b1 = *(float4*)&Bs[k][64 + tx * 4];
            float a[8] = {a0.x, a0.y, a0.z, a0.w, a1.x, a1.y, a1.z, a1.w};
            float b[8] = {b0.x, b0.y, b0.z, b0.w, b1.x, b1.y, b1.z, b1.w};
            #pragma unroll
            for (int i = 0; i < 8; i++)
                #pragma unroll
                for (int j = 0; j < 8; j++) acc[i][j] += a[i] * b[j];
        }
        __syncthreads();
    }
    #pragma unroll
    for (int i = 0; i < 8; i++) {
        int row = rowBase + ty * 8 + i;
        if (row < M) {
            float4 v0 = make_float4(acc[i][0], acc[i][1], acc[i][2], acc[i][3]);
            float4 v1 = make_float4(acc[i][4], acc[i][5], acc[i][6], acc[i][7]);
            *(float4*)(g_xw + ((size_t)(2 * rp) * NN + row) * 64 + tx * 4) = v0;
            *(float4*)(g_xw + ((size_t)(2 * rp + 1) * NN + row) * 64 + tx * 4) = v1;
        }
    }
}

// ---------------- scores: one warp per (r,n) ----------------
__global__ void k_scores(const float* __restrict__ q, const float* __restrict__ k) {
    int warp = (blockIdx.x * blockDim.x + threadIdx.x) >> 5;
    int lane = threadIdx.x & 31;
    if (warp >= RR * NN) return;
    float2 v  = ((const float2*)(g_xw + (size_t)warp * 64))[lane];
    float2 qv = ((const float2*)q)[lane];
    float2 kv = ((const float2*)k)[lane];
    float dq = v.x * qv.x + v.y * qv.y;
    float dk = v.x * kv.x + v.y * kv.y;
    #pragma unroll
    for (int off = 16; off; off >>= 1) {
        dq += __shfl_down_sync(0xffffffffu, dq, off);
        dk += __shfl_down_sync(0xffffffffu, dk, off);
    }
    if (lane == 0) { g_sq[warp] = dq; g_sk[warp] = dk; }
}

// ---------------- segmented softmax-aggregate: one warp per node ----------------
// mode 1: write g_x1 (device symbol referenced IN DEVICE CODE) + relu
// mode 0: write outParam (harness pointer)
__global__ void k_agg(const float* __restrict__ b, float* outParam, int mode) {
    int gw = (blockIdx.x * blockDim.x + threadIdx.x) >> 5;
    int lane = threadIdx.x & 31;
    if (gw >= NN) return;
    float* dst = (mode == 1) ? g_x1 : outParam;
    int node = gw;
    int beg = g_off[node];
    int cnt = g_cnt[node];

    // phase 1: segment max (lanes parallel over edges)
    float m = -INFINITY;
    for (int i = lane; i < cnt; i += 32) {
        int rs = g_sorted[beg + i];
        int r = rs / NN;
        float a = g_sq[r * NN + node] + g_sk[rs];
        a = a > 0.f ? a : 0.2f * a;
        m = fmaxf(m, a);
    }
    #pragma unroll
    for (int off = 16; off; off >>= 1)
        m = fmaxf(m, __shfl_xor_sync(0xffffffffu, m, off));
    if (cnt == 0) m = 0.f;

    // phase 2: whole warp per edge — gather 64 floats coalesced, accumulate
    float2 acc = make_float2(0.f, 0.f);
    float denom = 0.f;
    for (int i = 0; i < cnt; i++) {
        int rs = g_sorted[beg + i];                 // broadcast
        int r = rs / NN;
        float a = g_sq[r * NN + node] + g_sk[rs];   // broadcast gathers
        a = a > 0.f ? a : 0.2f * a;
        float w = __expf(a - m);
        denom += w;
        float2 v = ((const float2*)g_xw)[(size_t)rs * 32 + lane];
        acc.x += w * v.x;
        acc.y += w * v.y;
    }
    float inv = 1.f / (denom + 1e-16f);
    float2 bb = ((const float2*)b)[lane];
    float ox = acc.x * inv + bb.x;
    float oy = acc.y * inv + bb.y;
    if (mode == 1) { ox = fmaxf(ox, 0.f); oy = fmaxf(oy, 0.f); }
    ((float2*)dst)[(size_t)node * 32 + lane] = make_float2(ox, oy);
}

// ---------------- batchnorm ----------------
__global__ void k_bnstats(const float* __restrict__ out) {
    int gw = (blockIdx.x * blockDim.x + threadIdx.x) >> 5;   // 1024 warps
    int lane = threadIdx.x & 31;
    const int CHUNK = 98;                                     // 1024*98 >= 100000
    int n0 = gw * CHUNK;
    float2 s = make_float2(0.f, 0.f), s2 = make_float2(0.f, 0.f);
    for (int n = n0; n < n0 + CHUNK && n < NN; n++) {
        float2 v = ((const float2*)out)[(size_t)n * 32 + lane];
        s.x += v.x; s.y += v.y;
        s2.x += v.x * v.x; s2.y += v.y * v.y;
    }
    atomicAdd(&g_bnsum[2 * lane], s.x);     atomicAdd(&g_bnsum[2 * lane + 1], s.y);
    atomicAdd(&g_bnsqs[2 * lane], s2.x);    atomicAdd(&g_bnsqs[2 * lane + 1], s2.y);
}

__global__ void k_bnfinal(const float* __restrict__ gamma, const float* __restrict__ beta) {
    int h = threadIdx.x;
    if (h < HH) {
        float mean = g_bnsum[h] * (1.f / NN);
        float var  = g_bnsqs[h] * (1.f / NN) - mean * mean;
        float sc = gamma[h] * rsqrtf(var + 1e-5f);
        g_bnscale[h] = sc;
        g_bnshift[h] = beta[h] - mean * sc;
    }
}

__global__ void k_bnapply(float* __restrict__ out) {
    int t = blockIdx.x * blockDim.x + threadIdx.x;
    if (t >= NN * 16) return;
    int h4 = t & 15;
    float4 v  = ((float4*)out)[t];
    float4 sc = ((const float4*)g_bnscale)[h4];
    float4 sh = ((const float4*)g_bnshift)[h4];
    v.x = v.x * sc.x + sh.x; v.x = v.x > 0.f ? v.x : 0.01f * v.x;
    v.y = v.y * sc.y + sh.y; v.y = v.y > 0.f ? v.y : 0.01f * v.y;
    v.z = v.z * sc.z + sh.z; v.z = v.z > 0.f ? v.z : 0.01f * v.z;
    v.w = v.w * sc.w + sh.w; v.w = v.w > 0.f ? v.w : 0.01f * v.w;
    ((float4*)out)[t] = v;
}

// ---------------- launch ----------------
extern "C" void kernel_launch(void* const* d_in, const int* in_sizes, int n_in,
                              void* d_out, int out_size) {
    const float* x     = (const float*)d_in[0];
    const int*   ei    = (const int*)d_in[1];
    const int*   et    = (const int*)d_in[2];
    const float* W1    = (const float*)d_in[3];
    const float* q1    = (const float*)d_in[4];
    const float* k1    = (const float*)d_in[5];
    const float* b1    = (const float*)d_in[6];
    const float* W2    = (const float*)d_in[7];
    const float* q2    = (const float*)d_in[8];
    const float* k2    = (const float*)d_in[9];
    const float* b2    = (const float*)d_in[10];
    const float* gamma = (const float*)d_in[11];
    const float* beta  = (const float*)d_in[12];
    float* out = (float*)d_out;

    const int TPB = 256;
    dim3 gemmGrid(RR / 2, (NN + 127) / 128);

    // topology sort (once per call)
    k_zero<<<(NN + TPB - 1) / TPB, TPB>>>();
    k_decode<<<(EE + TPB - 1) / TPB, TPB>>>(ei, et);
    k_scan1<<<NBLK, SCAN_B>>>();
    k_scan2<<<1, 256>>>();
    k_scan3<<<(NN + TPB - 1) / TPB, TPB>>>();
    k_scatter<<<(EE + TPB - 1) / TPB, TPB>>>();

    // ---- layer 1 ----
    k_wt<<<(GG * CC + TPB - 1) / TPB, TPB>>>(W1, GG);
    k_gemm<<<gemmGrid, TPB>>>(x, NN, GG, 0);
    k_scores<<<(RR * NN * 32) / TPB, TPB>>>(q1, k1);
    k_agg<<<(NN * 32 + TPB - 1) / TPB, TPB>>>(b1, nullptr, 1);

    // ---- layer 2 ----
    k_wt<<<(HH * CC + TPB - 1) / TPB, TPB>>>(W2, HH);
    k_gemm<<<gemmGrid, TPB>>>(nullptr, NN, HH, 1);
    k_scores<<<(RR * NN * 32) / TPB, TPB>>>(q2, k2);
    k_agg<<<(NN * 32 + TPB - 1) / TPB, TPB>>>(b2, out, 0);

    // ---- batchnorm + leaky ----
    k_bnstats<<<(1024 * 32) / TPB, TPB>>>(out);
    k_bnfinal<<<1, HH>>>(gamma, beta);
    k_bnapply<<<(NN * 16 + TPB - 1) / TPB, TPB>>>(out);
}

// round 6
// speedup vs baseline: 1.7529x; 1.2156x over previous
#include <cuda_runtime.h>
#include <math.h>

#define NN 100000
#define EE 1600000
#define RR 8
#define GG 128
#define HH 64
#define CC 512   // RR*HH
#define SCAN_B 512
#define NBLK ((NN + SCAN_B - 1) / SCAN_B)   // 196

// ---------------- scratch ----------------
__device__ float g_xw[(size_t)RR * NN * HH];   // [r][n][h]
__device__ float g_WT[GG * CC];
__device__ float g_sq[RR * NN];
__device__ float g_sk[RR * NN];
__device__ int   g_rs[EE];                     // r*N + src
__device__ int   g_dstl[EE];
__device__ int   g_sorted[EE];                 // rs sorted by dst
__device__ int   g_cnt[NN];
__device__ int   g_wpos[NN];
__device__ int   g_off[NN];
__device__ int   g_scan[NN];
__device__ int   g_bsum[256];
__device__ int   g_bpre[256];
__device__ float g_x1[NN * HH];
__device__ float g_bnsum[HH];
__device__ float g_bnsqs[HH];
__device__ float g_bnscale[HH];
__device__ float g_bnshift[HH];

// ---------------- sort-by-dst pipeline ----------------
__global__ void k_zero() {
    int i = blockIdx.x * blockDim.x + threadIdx.x;
    if (i < NN) { g_cnt[i] = 0; g_wpos[i] = 0; }
    if (i < HH) { g_bnsum[i] = 0.f; g_bnsqs[i] = 0.f; }
}

__global__ void k_decode(const int* __restrict__ ei, const int* __restrict__ et) {
    int e = blockIdx.x * blockDim.x + threadIdx.x;
    if (e >= EE) return;
    int s = min(max(ei[e], 0), NN - 1);
    int d = min(max(ei[EE + e], 0), NN - 1);
    int r = min(max(et[e], 0), RR - 1);
    g_rs[e]   = r * NN + s;
    g_dstl[e] = d;
    atomicAdd(&g_cnt[d], 1);
}

__global__ void k_scan1() {
    __shared__ int s[SCAN_B];
    int tid = threadIdx.x;
    int i = blockIdx.x * SCAN_B + tid;
    int v = (i < NN) ? g_cnt[i] : 0;
    s[tid] = v;
    __syncthreads();
    for (int d = 1; d < SCAN_B; d <<= 1) {
        int t = (tid >= d) ? s[tid - d] : 0;
        __syncthreads();
        s[tid] += t;
        __syncthreads();
    }
    if (i < NN) g_scan[i] = s[tid];
    if (tid == SCAN_B - 1) g_bsum[blockIdx.x] = s[tid];
}

__global__ void k_scan2() {
    __shared__ int s[256];
    int tid = threadIdx.x;
    int v = (tid < NBLK) ? g_bsum[tid] : 0;
    s[tid] = v;
    __syncthreads();
    for (int d = 1; d < 256; d <<= 1) {
        int t = (tid >= d) ? s[tid - d] : 0;
        __syncthreads();
        s[tid] += t;
        __syncthreads();
    }
    if (tid < NBLK) g_bpre[tid] = s[tid] - v;   // exclusive
}

__global__ void k_scan3() {
    int i = blockIdx.x * blockDim.x + threadIdx.x;
    if (i >= NN) return;
    g_off[i] = g_scan[i] - g_cnt[i] + g_bpre[i >> 9];
}

__global__ void k_scatter() {
    int e = blockIdx.x * blockDim.x + threadIdx.x;
    if (e >= EE) return;
    int d = g_dstl[e];
    int pos = g_off[d] + atomicAdd(&g_wpos[d], 1);
    g_sorted[pos] = g_rs[e];
}

// ---------------- GEMM + fused scores ----------------
// W [R,K,H] -> WT [K, r*64+o]
__global__ void k_wt(const float* __restrict__ W, int K) {
    int idx = blockIdx.x * blockDim.x + threadIdx.x;
    if (idx >= K * CC) return;
    int i = idx / CC, c = idx % CC;
    int r = c >> 6, o = c & 63;
    g_WT[idx] = W[((size_t)r * K + i) * HH + o];
}

// 128 rows x 128 cols (2 relations), 8x8/thread; epilogue computes
// s_q[r,n] = xw[r,n,:].q and s_k likewise via half-warp reduction.
__global__ void k_gemm(const float* __restrict__ Aparam, int M, int K, int useX1,
                       const float* __restrict__ qv_g, const float* __restrict__ kv_g) {
    const float* __restrict__ A = useX1 ? g_x1 : Aparam;
    __shared__ float As[16][132];
    __shared__ float Bs[16][132];
    int rp = blockIdx.x;                 // relations 2rp, 2rp+1
    int rowBase = blockIdx.y * 128;
    int tid = threadIdx.x;
    int ty = tid >> 4, tx = tid & 15;
    float acc[8][8] = {};
    for (int kt = 0; kt < K; kt += 16) {
        #pragma unroll
        for (int p = 0; p < 2; p++) {
            int idx = tid + p * 256;
            int row = idx >> 2;
            int kq = (idx & 3) * 4;
            int grow = rowBase + row;
            float4 v = make_float4(0.f, 0.f, 0.f, 0.f);
            if (grow < M) v = *(const float4*)(A + (size_t)grow * K + kt + kq);
            As[kq + 0][row] = v.x; As[kq + 1][row] = v.y;
            As[kq + 2][row] = v.z; As[kq + 3][row] = v.w;
        }
        #pragma unroll
        for (int p = 0; p < 2; p++) {
            int idx = tid + p * 256;
            int kk = idx >> 5;
            int c4 = (idx & 31) * 4;
            float4 v = *(const float4*)(g_WT + (size_t)(kt + kk) * CC + rp * 128 + c4);
            *(float4*)&Bs[kk][c4] = v;
        }
        __syncthreads();
        #pragma unroll
        for (int k = 0; k < 16; k++) {
            float4 a0 = *(float4*)&As[k][ty * 8];
            float4 a1 = *(float4*)&As[k][ty * 8 + 4];
            float4 b0 = *(float4*)&Bs[k][tx * 4];
            float4 b1 = *(float4*)&Bs[k][64 + tx * 4];
            float a[8] = {a0.x, a0.y, a0.z, a0.w, a1.x, a1.y, a1.z, a1.w};
            float b[8] = {b0.x, b0.y, b0.z, b0.w, b1.x, b1.y, b1.z, b1.w};
            #pragma unroll
            for (int i = 0; i < 8; i++)
                #pragma unroll
                for (int j = 0; j < 8; j++) acc[i][j] += a[i] * b[j];
        }
        __syncthreads();
    }
    // store xw
    #pragma unroll
    for (int i = 0; i < 8; i++) {
        int row = rowBase + ty * 8 + i;
        if (row < M) {
            float4 v0 = make_float4(acc[i][0], acc[i][1], acc[i][2], acc[i][3]);
            float4 v1 = make_float4(acc[i][4], acc[i][5], acc[i][6], acc[i][7]);
            *(float4*)(g_xw + ((size_t)(2 * rp) * NN + row) * 64 + tx * 4) = v0;
            *(float4*)(g_xw + ((size_t)(2 * rp + 1) * NN + row) * 64 + tx * 4) = v1;
        }
    }
    // fused scores: q,k shared across relations
    float qv0 = qv_g[tx * 4 + 0], qv1 = qv_g[tx * 4 + 1],
          qv2 = qv_g[tx * 4 + 2], qv3 = qv_g[tx * 4 + 3];
    float kv0 = kv_g[tx * 4 + 0], kv1 = kv_g[tx * 4 + 1],
          kv2 = kv_g[tx * 4 + 2], kv3 = kv_g[tx * 4 + 3];
    #pragma unroll
    for (int i = 0; i < 8; i++) {
        float pq0 = acc[i][0] * qv0 + acc[i][1] * qv1 + acc[i][2] * qv2 + acc[i][3] * qv3;
        float pq1 = acc[i][4] * qv0 + acc[i][5] * qv1 + acc[i][6] * qv2 + acc[i][7] * qv3;
        float pk0 = acc[i][0] * kv0 + acc[i][1] * kv1 + acc[i][2] * kv2 + acc[i][3] * kv3;
        float pk1 = acc[i][4] * kv0 + acc[i][5] * kv1 + acc[i][6] * kv2 + acc[i][7] * kv3;
        #pragma unroll
        for (int off = 8; off; off >>= 1) {
            pq0 += __shfl_xor_sync(0xffffffffu, pq0, off);
            pq1 += __shfl_xor_sync(0xffffffffu, pq1, off);
            pk0 += __shfl_xor_sync(0xffffffffu, pk0, off);
            pk1 += __shfl_xor_sync(0xffffffffu, pk1, off);
        }
        int row = rowBase + ty * 8 + i;
        if (tx == 0 && row < M) {
            g_sq[(2 * rp) * NN + row]     = pq0;
            g_sq[(2 * rp + 1) * NN + row] = pq1;
            g_sk[(2 * rp) * NN + row]     = pk0;
            g_sk[(2 * rp + 1) * NN + row] = pk1;
        }
    }
}

// ---------------- segmented softmax-aggregate: one warp per node ----------------
__global__ void k_agg(const float* __restrict__ b, float* outParam, int mode) {
    int gw = (blockIdx.x * blockDim.x + threadIdx.x) >> 5;
    int lane = threadIdx.x & 31;
    if (gw >= NN) return;
    float* dst = (mode == 1) ? g_x1 : outParam;
    int node = gw;
    int beg = g_off[node];
    int cnt = g_cnt[node];

    float2 acc = make_float2(0.f, 0.f);
    float denom = 0.f;

    if (cnt <= 32) {
        // fast path: one edge per lane, alpha stays in registers
        int rs_l = 0;
        float a_l = -INFINITY;
        if (lane < cnt) {
            rs_l = g_sorted[beg + lane];
            int r = rs_l / NN;
            float a = g_sq[r * NN + node] + g_sk[rs_l];
            a_l = a > 0.f ? a : 0.2f * a;
        }
        float m = a_l;
        #pragma unroll
        for (int off = 16; off; off >>= 1)
            m = fmaxf(m, __shfl_xor_sync(0xffffffffu, m, off));
        float w_l = (lane < cnt) ? __expf(a_l - m) : 0.f;
        float ds = w_l;
        #pragma unroll
        for (int off = 16; off; off >>= 1)
            ds += __shfl_xor_sync(0xffffffffu, ds, off);
        denom = ds;
        int i = 0;
        for (; i + 2 <= cnt; i += 2) {
            int rs0 = __shfl_sync(0xffffffffu, rs_l, i);
            int rs1 = __shfl_sync(0xffffffffu, rs_l, i + 1);
            float w0 = __shfl_sync(0xffffffffu, w_l, i);
            float w1 = __shfl_sync(0xffffffffu, w_l, i + 1);
            float2 v0 = ((const float2*)g_xw)[(size_t)rs0 * 32 + lane];
            float2 v1 = ((const float2*)g_xw)[(size_t)rs1 * 32 + lane];
            acc.x += w0 * v0.x + w1 * v1.x;
            acc.y += w0 * v0.y + w1 * v1.y;
        }
        if (i < cnt) {
            int rs0 = __shfl_sync(0xffffffffu, rs_l, i);
            float w0 = __shfl_sync(0xffffffffu, w_l, i);
            float2 v0 = ((const float2*)g_xw)[(size_t)rs0 * 32 + lane];
            acc.x += w0 * v0.x;
            acc.y += w0 * v0.y;
        }
    } else {
        // general path
        float m = -INFINITY;
        for (int i = lane; i < cnt; i += 32) {
            int rs = g_sorted[beg + i];
            int r = rs / NN;
            float a = g_sq[r * NN + node] + g_sk[rs];
            a = a > 0.f ? a : 0.2f * a;
            m = fmaxf(m, a);
        }
        #pragma unroll
        for (int off = 16; off; off >>= 1)
            m = fmaxf(m, __shfl_xor_sync(0xffffffffu, m, off));
        for (int i = 0; i < cnt; i++) {
            int rs = g_sorted[beg + i];
            int r = rs / NN;
            float a = g_sq[r * NN + node] + g_sk[rs];
            a = a > 0.f ? a : 0.2f * a;
            float w = __expf(a - m);
            denom += w;
            float2 v = ((const float2*)g_xw)[(size_t)rs * 32 + lane];
            acc.x += w * v.x;
            acc.y += w * v.y;
        }
    }

    float inv = 1.f / (denom + 1e-16f);
    float2 bb = ((const float2*)b)[lane];
    float ox = acc.x * inv + bb.x;
    float oy = acc.y * inv + bb.y;
    if (mode == 1) { ox = fmaxf(ox, 0.f); oy = fmaxf(oy, 0.f); }
    ((float2*)dst)[(size_t)node * 32 + lane] = make_float2(ox, oy);
}

// ---------------- batchnorm ----------------
__global__ void k_bnstats(const float* __restrict__ out) {
    int gw = (blockIdx.x * blockDim.x + threadIdx.x) >> 5;   // 1024 warps
    int lane = threadIdx.x & 31;
    const int CHUNK = 98;
    int n0 = gw * CHUNK;
    float2 s = make_float2(0.f, 0.f), s2 = make_float2(0.f, 0.f);
    for (int n = n0; n < n0 + CHUNK && n < NN; n++) {
        float2 v = ((const float2*)out)[(size_t)n * 32 + lane];
        s.x += v.x; s.y += v.y;
        s2.x += v.x * v.x; s2.y += v.y * v.y;
    }
    atomicAdd(&g_bnsum[2 * lane], s.x);     atomicAdd(&g_bnsum[2 * lane + 1], s.y);
    atomicAdd(&g_bnsqs[2 * lane], s2.x);    atomicAdd(&g_bnsqs[2 * lane + 1], s2.y);
}

__global__ void k_bnfinal(const float* __restrict__ gamma, const float* __restrict__ beta) {
    int h = threadIdx.x;
    if (h < HH) {
        float mean = g_bnsum[h] * (1.f / NN);
        float var  = g_bnsqs[h] * (1.f / NN) - mean * mean;
        float sc = gamma[h] * rsqrtf(var + 1e-5f);
        g_bnscale[h] = sc;
        g_bnshift[h] = beta[h] - mean * sc;
    }
}

__global__ void k_bnapply(float* __restrict__ out) {
    int t = blockIdx.x * blockDim.x + threadIdx.x;
    if (t >= NN * 16) return;
    int h4 = t & 15;
    float4 v  = ((float4*)out)[t];
    float4 sc = ((const float4*)g_bnscale)[h4];
    float4 sh = ((const float4*)g_bnshift)[h4];
    v.x = v.x * sc.x + sh.x; v.x = v.x > 0.f ? v.x : 0.01f * v.x;
    v.y = v.y * sc.y + sh.y; v.y = v.y > 0.f ? v.y : 0.01f * v.y;
    v.z = v.z * sc.z + sh.z; v.z = v.z > 0.f ? v.z : 0.01f * v.z;
    v.w = v.w * sc.w + sh.w; v.w = v.w > 0.f ? v.w : 0.01f * v.w;
    ((float4*)out)[t] = v;
}

// ---------------- launch ----------------
extern "C" void kernel_launch(void* const* d_in, const int* in_sizes, int n_in,
                              void* d_out, int out_size) {
    const float* x     = (const float*)d_in[0];
    const int*   ei    = (const int*)d_in[1];
    const int*   et    = (const int*)d_in[2];
    const float* W1    = (const float*)d_in[3];
    const float* q1    = (const float*)d_in[4];
    const float* k1    = (const float*)d_in[5];
    const float* b1    = (const float*)d_in[6];
    const float* W2    = (const float*)d_in[7];
    const float* q2    = (const float*)d_in[8];
    const float* k2    = (const float*)d_in[9];
    const float* b2    = (const float*)d_in[10];
    const float* gamma = (const float*)d_in[11];
    const float* beta  = (const float*)d_in[12];
    float* out = (float*)d_out;

    const int TPB = 256;
    dim3 gemmGrid(RR / 2, (NN + 127) / 128);

    // topology sort
    k_zero<<<(NN + TPB - 1) / TPB, TPB>>>();
    k_decode<<<(EE + TPB - 1) / TPB, TPB>>>(ei, et);
    k_scan1<<<NBLK, SCAN_B>>>();
    k_scan2<<<1, 256>>>();
    k_scan3<<<(NN + TPB - 1) / TPB, TPB>>>();
    k_scatter<<<(EE + TPB - 1) / TPB, TPB>>>();

    // ---- layer 1 ----
    k_wt<<<(GG * CC + TPB - 1) / TPB, TPB>>>(W1, GG);
    k_gemm<<<gemmGrid, TPB>>>(x, NN, GG, 0, q1, k1);
    k_agg<<<(NN * 32 + TPB - 1) / TPB, TPB>>>(b1, nullptr, 1);

    // ---- layer 2 ----
    k_wt<<<(HH * CC + TPB - 1) / TPB, TPB>>>(W2, HH);
    k_gemm<<<gemmGrid, TPB>>>(nullptr, NN, HH, 1, q2, k2);
    k_agg<<<(NN * 32 + TPB - 1) / TPB, TPB>>>(b2, out, 0);

    // ---- batchnorm + leaky ----
    k_bnstats<<<(1024 * 32) / TPB, TPB>>>(out);
    k_bnfinal<<<1, HH>>>(gamma, beta);
    k_bnapply<<<(NN * 16 + TPB - 1) / TPB, TPB>>>(out);
}